// round 12
// baseline (speedup 1.0000x reference)
#include <cuda_runtime.h>
#include <cstdint>

#define B_   4
#define L_   2048
#define H_   8
#define D_   64
#define NS   40
#define NBH  (B_*H_)
#define NQB  10          // queries per update block
#define NGRP 4           // grid 128 -> single wave, minimal K/V duplication
#define UT   1024        // update threads

__device__ float g_M[NBH*L_];
__device__ int   g_top[NBH*NS];

// ---------------- packed f32x2 helpers ----------------
__device__ __forceinline__ void fma2(unsigned long long& d,
                                     unsigned long long a, unsigned long long b) {
    asm("fma.rn.f32x2 %0, %1, %2, %0;" : "+l"(d) : "l"(a), "l"(b));
}
__device__ __forceinline__ unsigned long long pack2(float lo, float hi) {
    unsigned long long r;
    asm("mov.b64 %0, {%1, %2};" : "=l"(r) : "f"(lo), "f"(hi));
    return r;
}
__device__ __forceinline__ void unpack2(unsigned long long p, float& lo, float& hi) {
    asm("mov.b64 {%0, %1}, %2;" : "=f"(lo), "=f"(hi) : "l"(p));
}

// ---------------- threefry2x32 ----------------
__device__ __forceinline__ uint32_t rotl32(uint32_t x, int r) {
    return (x << r) | (x >> (32 - r));
}
__device__ __forceinline__ void threefry2x32(uint32_t k0, uint32_t k1,
                                             uint32_t c0, uint32_t c1,
                                             uint32_t& o0, uint32_t& o1) {
    uint32_t ks0 = k0, ks1 = k1, ks2 = k0 ^ k1 ^ 0x1BD11BDAu;
    uint32_t x0 = c0 + ks0, x1 = c1 + ks1;
#define TF_RND(R) { x0 += x1; x1 = rotl32(x1, R); x1 ^= x0; }
    TF_RND(13) TF_RND(15) TF_RND(26) TF_RND(6)  x0 += ks1; x1 += ks2 + 1u;
    TF_RND(17) TF_RND(29) TF_RND(16) TF_RND(24) x0 += ks2; x1 += ks0 + 2u;
    TF_RND(13) TF_RND(15) TF_RND(26) TF_RND(6)  x0 += ks0; x1 += ks1 + 3u;
    TF_RND(17) TF_RND(29) TF_RND(16) TF_RND(24) x0 += ks1; x1 += ks2 + 4u;
    TF_RND(13) TF_RND(15) TF_RND(26) TF_RND(6)  x0 += ks2; x1 += ks0 + 5u;
#undef TF_RND
    o0 = x0; o1 = x1;
}

// K1: M = max - mean of sampled dots. Block=(b,q), warp=head. (unchanged)
__global__ void kernel_M(const float* __restrict__ q, const float* __restrict__ k) {
    int blk = blockIdx.x;
    int b   = blk >> 11;
    int qi  = blk & (L_ - 1);
    int w   = threadIdx.x >> 5;
    int lane = threadIdx.x & 31;
    int g = lane >> 3;
    int r = lane & 7;

    __shared__ int sidx[NS];
    if (threadIdx.x < NS) {
        uint32_t k20, k21;
        threefry2x32(0u, 42u, 0u, 1u, k20, k21);
        uint32_t a, bb;
        threefry2x32(k20, k21, 0u, (uint32_t)(qi * NS + threadIdx.x), a, bb);
        sidx[threadIdx.x] = (int)((a ^ bb) & 2047u);
    }
    __syncthreads();

    const float4* q4 = (const float4*)(q + (((size_t)blk) * H_ + w) * D_);
    float4 qa = q4[r], qb = q4[r + 8];

    const float4* kbase = (const float4*)k + ((size_t)b * L_) * (H_ * D_ / 4) + w * (D_ / 4);

    float mx = -INFINITY, sm = 0.0f;
#pragma unroll 2
    for (int s0 = 0; s0 < NS; s0 += 4) {
        int j = sidx[s0 + g];
        const float4* kr = kbase + (size_t)j * (H_ * D_ / 4);
        float4 ka = __ldg(&kr[r]);
        float4 kb = __ldg(&kr[r + 8]);
        float p = ka.x * qa.x + ka.y * qa.y + ka.z * qa.z + ka.w * qa.w
                + kb.x * qb.x + kb.y * qb.y + kb.z * qb.z + kb.w * qb.w;
        p += __shfl_xor_sync(0xffffffffu, p, 4);
        p += __shfl_xor_sync(0xffffffffu, p, 2);
        p += __shfl_xor_sync(0xffffffffu, p, 1);
        mx = fmaxf(mx, p);
        sm += p;
    }
    mx = fmaxf(mx, __shfl_xor_sync(0xffffffffu, mx, 8));
    mx = fmaxf(mx, __shfl_xor_sync(0xffffffffu, mx, 16));
    sm += __shfl_xor_sync(0xffffffffu, sm, 8);
    sm += __shfl_xor_sync(0xffffffffu, sm, 16);
    if (lane == 0) g_M[(b * H_ + w) * L_ + qi] = mx - sm * (1.0f / (float)NS);
}

// K2: top-40 per (b,h). (unchanged)
__global__ void kernel_topk() {
    int bh = blockIdx.x, t = threadIdx.x;
    float vals[8];
#pragma unroll
    for (int i = 0; i < 8; i++) vals[i] = g_M[bh * L_ + t * 8 + i];

    __shared__ float wv[8];
    __shared__ int   wi[8];
    __shared__ int   sbi;
    int warp = t >> 5, lane = t & 31;

    for (int u = 0; u < NS; u++) {
        float bv = -INFINITY; int bi = 1 << 30;
#pragma unroll
        for (int i = 0; i < 8; i++) {
            if (vals[i] > bv) { bv = vals[i]; bi = t * 8 + i; }
        }
#pragma unroll
        for (int o = 16; o; o >>= 1) {
            float ov = __shfl_xor_sync(0xffffffffu, bv, o);
            int   oi = __shfl_xor_sync(0xffffffffu, bi, o);
            if (ov > bv || (ov == bv && oi < bi)) { bv = ov; bi = oi; }
        }
        if (lane == 0) { wv[warp] = bv; wi[warp] = bi; }
        __syncthreads();
        if (t == 0) {
            float fb = wv[0]; int fi = wi[0];
#pragma unroll
            for (int wd = 1; wd < 8; wd++) {
                if (wv[wd] > fb || (wv[wd] == fb && wi[wd] < fi)) { fb = wv[wd]; fi = wi[wd]; }
            }
            g_top[bh * NS + u] = fi;
            sbi = fi;
        }
        __syncthreads();
        int fi = sbi;
        if ((fi >> 3) == t) vals[fi & 7] = -INFINITY;
        __syncthreads();
    }
}

// K3: fused V_mean + broadcast-init. (unchanged)
__global__ __launch_bounds__(512) void kernel_vmean_init(const float* __restrict__ v,
                                                         float* __restrict__ out) {
    __shared__ float4 sred[512];
    __shared__ float4 vm4[16];
    int bh = blockIdx.x >> 2, quarter = blockIdx.x & 3;
    int b = bh >> 3, h = bh & 7;
    int t = threadIdx.x;
    int d4 = t & 15, r = t >> 4;

    const float4* v4 = (const float4*)v;
    size_t base = ((size_t)b * L_) * (H_ * D_ / 4) + h * (D_ / 4) + d4;
    float4 acc = make_float4(0.f, 0.f, 0.f, 0.f);
#pragma unroll 8
    for (int it = 0; it < L_ / 32; it++) {
        float4 x = __ldg(&v4[base + (size_t)(it * 32 + r) * (H_ * D_ / 4)]);
        acc.x += x.x; acc.y += x.y; acc.z += x.z; acc.w += x.w;
    }
    sred[t] = acc;
    __syncthreads();
    for (int o = 256; o >= 16; o >>= 1) {
        if (t < o) {
            float4 a = sred[t], bb = sred[t + o];
            a.x += bb.x; a.y += bb.y; a.z += bb.z; a.w += bb.w;
            sred[t] = a;
        }
        __syncthreads();
    }
    if (t < 16) {
        float4 s = sred[t];
        const float inv = 1.0f / (float)L_;
        s.x *= inv; s.y *= inv; s.z *= inv; s.w *= inv;
        vm4[t] = s;
    }
    __syncthreads();
    float4* out4 = (float4*)out;
    for (int e = t; e < 512 * 16; e += 512) {
        int l = quarter * 512 + (e >> 4), c = e & 15;
        out4[(((size_t)b * L_ + l) * H_ + h) * 16 + c] = vm4[c];
    }
}

// K4: dense attention, 10 queries/block, grid 128, 1024 threads (32 warps/SM).
__global__ __launch_bounds__(UT, 1) void kernel_update(const float* __restrict__ q,
                                                       const float* __restrict__ k,
                                                       const float* __restrict__ v,
                                                       float* __restrict__ out) {
    extern __shared__ float sh[];
    float* s_sc   = sh;                      // NQB * 2048 (80KB)
    float* s_q    = s_sc + NQB * L_;         // 640
    float* s_vout = s_q + NQB * D_;          // NQB * 16 * 64 (40KB)
    float* s_red  = s_vout + NQB * 16 * D_;  // 64: m-halves[0..19], l-halves[32..51]

    int bx  = blockIdx.x;
    int bh  = bx >> 2;
    int grp = bx & 3;
    int b = bh >> 3, h = bh & 7;
    int t = threadIdx.x;
    int w = t >> 5, lane = t & 31;

    // stage the 10 selected q rows
    if (t < NQB * D_) {
        int i = t >> 6, d = t & 63;
        int qx = __ldg(&g_top[bh * NS + grp * NQB + i]);
        s_q[t] = q[(((size_t)b * L_ + qx) * H_ + h) * D_ + d];
    }
    __syncthreads();

    // scores: 10 q x 2048 k, packed f32x2. 2 reps of 1024 keys.
    const ulonglong2* k16 = (const ulonglong2*)k;
    const ulonglong2* q16 = (const ulonglong2*)s_q;
#pragma unroll 1
    for (int rep = 0; rep < 2; rep++) {
        int j = rep * UT + t;
        const ulonglong2* kr = k16 + (((size_t)b * L_ + j) * H_ + h) * 16;
        unsigned long long acc2[NQB];
#pragma unroll
        for (int i = 0; i < NQB; i++) acc2[i] = 0ull;
#pragma unroll
        for (int dv = 0; dv < 16; dv++) {
            ulonglong2 kv = kr[dv];
#pragma unroll
            for (int i = 0; i < NQB; i++) {
                ulonglong2 qv = q16[i * 16 + dv];
                fma2(acc2[i], kv.x, qv.x);
                fma2(acc2[i], kv.y, qv.y);
            }
        }
#pragma unroll
        for (int i = 0; i < NQB; i++) {
            float lo, hi; unpack2(acc2[i], lo, hi);
            s_sc[i * L_ + j] = (lo + hi) * 0.125f;
        }
    }
    __syncthreads();

    // softmax: 20 warps own half-rows (1024 elems each); uniform barriers
    {
        bool act = (w < 2 * NQB);
        int r = w >> 1, hf = w & 1;
        float* sc = s_sc + r * L_ + hf * 1024;
        if (act) {
            float m = -INFINITY;
#pragma unroll
            for (int ii = 0; ii < 32; ii++) m = fmaxf(m, sc[ii * 32 + lane]);
#pragma unroll
            for (int o = 16; o; o >>= 1) m = fmaxf(m, __shfl_xor_sync(0xffffffffu, m, o));
            if (lane == 0) s_red[w] = m;
        }
        __syncthreads();
        if (act) {
            float gm = fmaxf(s_red[r << 1], s_red[(r << 1) | 1]);
            float l = 0.0f;
#pragma unroll
            for (int ii = 0; ii < 32; ii++) {
                int jj = ii * 32 + lane;
                float e = __expf(sc[jj] - gm);
                sc[jj] = e;
                l += e;
            }
#pragma unroll
            for (int o = 16; o; o >>= 1) l += __shfl_xor_sync(0xffffffffu, l, o);
            if (lane == 0) s_red[32 + w] = l;
        }
        __syncthreads();
    }

    // attn @ V (unnormalized): d = t&63, key-chunk c = t>>6 (16 chunks of 128).
    // 4 keys/iter; score reads are warp-broadcast LDS.128.
    int d = t & 63, c = t >> 6;
    unsigned long long accu[NQB];
#pragma unroll
    for (int i = 0; i < NQB; i++) accu[i] = 0ull;
    const float* vb = v + (((size_t)b * L_ + c * 128) * H_ + h) * D_ + d;
#pragma unroll 2
    for (int jj = 0; jj < 32; jj++) {
        float v0 = __ldg(&vb[(size_t)(jj * 4 + 0) * (H_ * D_)]);
        float v1 = __ldg(&vb[(size_t)(jj * 4 + 1) * (H_ * D_)]);
        float v2 = __ldg(&vb[(size_t)(jj * 4 + 2) * (H_ * D_)]);
        float v3 = __ldg(&vb[(size_t)(jj * 4 + 3) * (H_ * D_)]);
        unsigned long long vp01 = pack2(v0, v1);
        unsigned long long vp23 = pack2(v2, v3);
        int j0 = c * 128 + jj * 4;
#pragma unroll
        for (int i = 0; i < NQB; i++) {
            ulonglong2 ap = *(const ulonglong2*)(s_sc + i * L_ + j0);
            fma2(accu[i], ap.x, vp01);
            fma2(accu[i], ap.y, vp23);
        }
    }
#pragma unroll
    for (int i = 0; i < NQB; i++) {
        float lo, hi; unpack2(accu[i], lo, hi);
        s_vout[(i * 16 + c) * 64 + d] = lo + hi;
    }
    __syncthreads();

    // cross-chunk reduce + normalize + write (640 outputs)
    if (t < NQB * D_) {
        int i = t >> 6, dd = t & 63;
        float inv = 1.0f / (s_red[32 + (i << 1)] + s_red[32 + (i << 1) + 1]);
        float tot = 0.0f;
#pragma unroll
        for (int cc = 0; cc < 16; cc++) tot += s_vout[(i * 16 + cc) * 64 + dd];
        int qx = __ldg(&g_top[bh * NS + grp * NQB + i]);
        out[(((size_t)b * L_ + qx) * H_ + h) * D_ + dd] = tot * inv;
    }
}

extern "C" void kernel_launch(void* const* d_in, const int* in_sizes, int n_in,
                              void* d_out, int out_size) {
    const float* q = (const float*)d_in[0];
    const float* k = (const float*)d_in[1];
    const float* v = (const float*)d_in[2];
    float* out = (float*)d_out;

    static const size_t upd_smem =
        (size_t)(NQB * L_ + NQB * D_ + NQB * 16 * D_ + 64) * sizeof(float);
    cudaFuncSetAttribute(kernel_update, cudaFuncAttributeMaxDynamicSharedMemorySize, (int)upd_smem);

    kernel_vmean_init<<<NBH * 4, 512>>>(v, out);
    kernel_M<<<B_ * L_, 256>>>(q, k);
    kernel_topk<<<NBH, 256>>>();
    kernel_update<<<NBH * NGRP, UT, upd_smem>>>(q, k, v, out);
}

// round 13
// speedup vs baseline: 2.3000x; 2.3000x over previous
#include <cuda_runtime.h>
#include <cstdint>

#define B_   4
#define L_   2048
#define H_   8
#define D_   64
#define NS   40
#define NBH  (B_*H_)
#define NQB  10          // queries per update block
#define NGRP 4           // groups -> grid 128 (single wave on 148 SMs)

__device__ float g_M[NBH*L_];
__device__ int   g_top[NBH*NS];

// ---------------- packed f32x2 helpers ----------------
__device__ __forceinline__ void fma2(unsigned long long& d,
                                     unsigned long long a, unsigned long long b) {
    asm("fma.rn.f32x2 %0, %1, %2, %0;" : "+l"(d) : "l"(a), "l"(b));
}
__device__ __forceinline__ unsigned long long pack2(float lo, float hi) {
    unsigned long long r;
    asm("mov.b64 %0, {%1, %2};" : "=l"(r) : "f"(lo), "f"(hi));
    return r;
}
__device__ __forceinline__ void unpack2(unsigned long long p, float& lo, float& hi) {
    asm("mov.b64 {%0, %1}, %2;" : "=f"(lo), "=f"(hi) : "l"(p));
}

// ---------------- threefry2x32 ----------------
__device__ __forceinline__ uint32_t rotl32(uint32_t x, int r) {
    return (x << r) | (x >> (32 - r));
}
__device__ __forceinline__ void threefry2x32(uint32_t k0, uint32_t k1,
                                             uint32_t c0, uint32_t c1,
                                             uint32_t& o0, uint32_t& o1) {
    uint32_t ks0 = k0, ks1 = k1, ks2 = k0 ^ k1 ^ 0x1BD11BDAu;
    uint32_t x0 = c0 + ks0, x1 = c1 + ks1;
#define TF_RND(R) { x0 += x1; x1 = rotl32(x1, R); x1 ^= x0; }
    TF_RND(13) TF_RND(15) TF_RND(26) TF_RND(6)  x0 += ks1; x1 += ks2 + 1u;
    TF_RND(17) TF_RND(29) TF_RND(16) TF_RND(24) x0 += ks2; x1 += ks0 + 2u;
    TF_RND(13) TF_RND(15) TF_RND(26) TF_RND(6)  x0 += ks0; x1 += ks1 + 3u;
    TF_RND(17) TF_RND(29) TF_RND(16) TF_RND(24) x0 += ks1; x1 += ks2 + 4u;
    TF_RND(13) TF_RND(15) TF_RND(26) TF_RND(6)  x0 += ks2; x1 += ks0 + 5u;
#undef TF_RND
    o0 = x0; o1 = x1;
}

// K1: M = max - mean of sampled dots. Block=(b,q), warp=head. (R9, unchanged)
__global__ void kernel_M(const float* __restrict__ q, const float* __restrict__ k) {
    int blk = blockIdx.x;
    int b   = blk >> 11;
    int qi  = blk & (L_ - 1);
    int w   = threadIdx.x >> 5;
    int lane = threadIdx.x & 31;
    int g = lane >> 3;
    int r = lane & 7;

    __shared__ int sidx[NS];
    if (threadIdx.x < NS) {
        uint32_t k20, k21;
        threefry2x32(0u, 42u, 0u, 1u, k20, k21);
        uint32_t a, bb;
        threefry2x32(k20, k21, 0u, (uint32_t)(qi * NS + threadIdx.x), a, bb);
        sidx[threadIdx.x] = (int)((a ^ bb) & 2047u);
    }
    __syncthreads();

    const float4* q4 = (const float4*)(q + (((size_t)blk) * H_ + w) * D_);
    float4 qa = q4[r], qb = q4[r + 8];

    const float4* kbase = (const float4*)k + ((size_t)b * L_) * (H_ * D_ / 4) + w * (D_ / 4);

    float mx = -INFINITY, sm = 0.0f;
#pragma unroll 2
    for (int s0 = 0; s0 < NS; s0 += 4) {
        int j = sidx[s0 + g];
        const float4* kr = kbase + (size_t)j * (H_ * D_ / 4);
        float4 ka = __ldg(&kr[r]);
        float4 kb = __ldg(&kr[r + 8]);
        float p = ka.x * qa.x + ka.y * qa.y + ka.z * qa.z + ka.w * qa.w
                + kb.x * qb.x + kb.y * qb.y + kb.z * qb.z + kb.w * qb.w;
        p += __shfl_xor_sync(0xffffffffu, p, 4);
        p += __shfl_xor_sync(0xffffffffu, p, 2);
        p += __shfl_xor_sync(0xffffffffu, p, 1);
        mx = fmaxf(mx, p);
        sm += p;
    }
    mx = fmaxf(mx, __shfl_xor_sync(0xffffffffu, mx, 8));
    mx = fmaxf(mx, __shfl_xor_sync(0xffffffffu, mx, 16));
    sm += __shfl_xor_sync(0xffffffffu, sm, 8);
    sm += __shfl_xor_sync(0xffffffffu, sm, 16);
    if (lane == 0) g_M[(b * H_ + w) * L_ + qi] = mx - sm * (1.0f / (float)NS);
}

// K2: top-40 per (b,h). (unchanged)
__global__ void kernel_topk() {
    int bh = blockIdx.x, t = threadIdx.x;
    float vals[8];
#pragma unroll
    for (int i = 0; i < 8; i++) vals[i] = g_M[bh * L_ + t * 8 + i];

    __shared__ float wv[8];
    __shared__ int   wi[8];
    __shared__ int   sbi;
    int warp = t >> 5, lane = t & 31;

    for (int u = 0; u < NS; u++) {
        float bv = -INFINITY; int bi = 1 << 30;
#pragma unroll
        for (int i = 0; i < 8; i++) {
            if (vals[i] > bv) { bv = vals[i]; bi = t * 8 + i; }
        }
#pragma unroll
        for (int o = 16; o; o >>= 1) {
            float ov = __shfl_xor_sync(0xffffffffu, bv, o);
            int   oi = __shfl_xor_sync(0xffffffffu, bi, o);
            if (ov > bv || (ov == bv && oi < bi)) { bv = ov; bi = oi; }
        }
        if (lane == 0) { wv[warp] = bv; wi[warp] = bi; }
        __syncthreads();
        if (t == 0) {
            float fb = wv[0]; int fi = wi[0];
#pragma unroll
            for (int wd = 1; wd < 8; wd++) {
                if (wv[wd] > fb || (wv[wd] == fb && wi[wd] < fi)) { fb = wv[wd]; fi = wi[wd]; }
            }
            g_top[bh * NS + u] = fi;
            sbi = fi;
        }
        __syncthreads();
        int fi = sbi;
        if ((fi >> 3) == t) vals[fi & 7] = -INFINITY;
        __syncthreads();
    }
}

// K3: fused V_mean + broadcast-init. (unchanged)
__global__ __launch_bounds__(512) void kernel_vmean_init(const float* __restrict__ v,
                                                         float* __restrict__ out) {
    __shared__ float4 sred[512];
    __shared__ float4 vm4[16];
    int bh = blockIdx.x >> 2, quarter = blockIdx.x & 3;
    int b = bh >> 3, h = bh & 7;
    int t = threadIdx.x;
    int d4 = t & 15, r = t >> 4;

    const float4* v4 = (const float4*)v;
    size_t base = ((size_t)b * L_) * (H_ * D_ / 4) + h * (D_ / 4) + d4;
    float4 acc = make_float4(0.f, 0.f, 0.f, 0.f);
#pragma unroll 8
    for (int it = 0; it < L_ / 32; it++) {
        float4 x = __ldg(&v4[base + (size_t)(it * 32 + r) * (H_ * D_ / 4)]);
        acc.x += x.x; acc.y += x.y; acc.z += x.z; acc.w += x.w;
    }
    sred[t] = acc;
    __syncthreads();
    for (int o = 256; o >= 16; o >>= 1) {
        if (t < o) {
            float4 a = sred[t], bb = sred[t + o];
            a.x += bb.x; a.y += bb.y; a.z += bb.z; a.w += bb.w;
            sred[t] = a;
        }
        __syncthreads();
    }
    if (t < 16) {
        float4 s = sred[t];
        const float inv = 1.0f / (float)L_;
        s.x *= inv; s.y *= inv; s.z *= inv; s.w *= inv;
        vm4[t] = s;
    }
    __syncthreads();
    float4* out4 = (float4*)out;
    for (int e = t; e < 512 * 16; e += 512) {
        int l = quarter * 512 + (e >> 4), c = e & 15;
        out4[(((size_t)b * L_ + l) * H_ + h) * 16 + c] = vm4[c];
    }
}

// K4: dense attention, 10 queries/block, grid 128 (single wave). 512 threads.
// R9 structure, natural register allocation (no launch bound), quad-key AV.
__global__ __launch_bounds__(512) void kernel_update(const float* __restrict__ q,
                                                     const float* __restrict__ k,
                                                     const float* __restrict__ v,
                                                     float* __restrict__ out) {
    extern __shared__ float sh[];
    float* s_sc   = sh;                     // NQB * 2048
    float* s_q    = s_sc + NQB * L_;        // NQB * 64
    float* s_vout = s_q + NQB * D_;         // NQB * 8 * 64
    float* s_red  = s_vout + NQB * 8 * D_;  // 2*NQB (m, l)

    int bx  = blockIdx.x;
    int bh  = bx >> 2;
    int grp = bx & 3;
    int b = bh >> 3, h = bh & 7;
    int t = threadIdx.x;
    int w = t >> 5, lane = t & 31;

    // stage the 10 selected q rows
    for (int e = t; e < NQB * D_; e += 512) {
        int i = e >> 6, d = e & 63;
        int qx = __ldg(&g_top[bh * NS + grp * NQB + i]);
        s_q[e] = q[(((size_t)b * L_ + qx) * H_ + h) * D_ + d];
    }
    __syncthreads();

    // scores: 10 q x 2048 k, packed f32x2
    const ulonglong2* k16 = (const ulonglong2*)k;
    const ulonglong2* q16 = (const ulonglong2*)s_q;
#pragma unroll 1
    for (int rep = 0; rep < 4; rep++) {
        int j = rep * 512 + t;
        const ulonglong2* kr = k16 + (((size_t)b * L_ + j) * H_ + h) * 16;
        unsigned long long acc2[NQB];
#pragma unroll
        for (int i = 0; i < NQB; i++) acc2[i] = 0ull;
#pragma unroll
        for (int dv = 0; dv < 16; dv++) {
            ulonglong2 kv = kr[dv];
#pragma unroll
            for (int i = 0; i < NQB; i++) {
                ulonglong2 qv = q16[i * 16 + dv];
                fma2(acc2[i], kv.x, qv.x);
                fma2(acc2[i], kv.y, qv.y);
            }
        }
#pragma unroll
        for (int i = 0; i < NQB; i++) {
            float lo, hi; unpack2(acc2[i], lo, hi);
            s_sc[i * L_ + j] = (lo + hi) * 0.125f;
        }
    }
    __syncthreads();

    // softmax: warp w owns row w (w < NQB), full 2048 row
    if (w < NQB) {
        float* sc = s_sc + w * L_;
        float m = -INFINITY;
#pragma unroll
        for (int ii = 0; ii < 64; ii++) m = fmaxf(m, sc[ii * 32 + lane]);
#pragma unroll
        for (int o = 16; o; o >>= 1) m = fmaxf(m, __shfl_xor_sync(0xffffffffu, m, o));
        float l = 0.0f;
#pragma unroll
        for (int ii = 0; ii < 64; ii++) {
            int jj = ii * 32 + lane;
            float e = __expf(sc[jj] - m);
            sc[jj] = e;
            l += e;
        }
#pragma unroll
        for (int o = 16; o; o >>= 1) l += __shfl_xor_sync(0xffffffffu, l, o);
        if (lane == 0) { s_red[w] = m; s_red[NQB + w] = l; }
    }
    __syncthreads();

    // attn @ V (unnormalized): d = t&63, key-chunk c = t>>6 (8 chunks of 256).
    // 4 keys/iter: one broadcast LDS.128 per query per quad; unroll 2 -> 8 LDGs in flight.
    int d = t & 63, c = t >> 6;
    unsigned long long accu[NQB];
#pragma unroll
    for (int i = 0; i < NQB; i++) accu[i] = 0ull;
    const float* vb = v + (((size_t)b * L_ + c * 256) * H_ + h) * D_ + d;
#pragma unroll 2
    for (int jj = 0; jj < 64; jj++) {
        float v0 = __ldg(&vb[(size_t)(jj * 4 + 0) * (H_ * D_)]);
        float v1 = __ldg(&vb[(size_t)(jj * 4 + 1) * (H_ * D_)]);
        float v2 = __ldg(&vb[(size_t)(jj * 4 + 2) * (H_ * D_)]);
        float v3 = __ldg(&vb[(size_t)(jj * 4 + 3) * (H_ * D_)]);
        unsigned long long vp01 = pack2(v0, v1);
        unsigned long long vp23 = pack2(v2, v3);
        int j0 = c * 256 + jj * 4;
#pragma unroll
        for (int i = 0; i < NQB; i++) {
            ulonglong2 ap = *(const ulonglong2*)(s_sc + i * L_ + j0);
            fma2(accu[i], ap.x, vp01);
            fma2(accu[i], ap.y, vp23);
        }
    }
#pragma unroll
    for (int i = 0; i < NQB; i++) {
        float lo, hi; unpack2(accu[i], lo, hi);
        s_vout[(i * 8 + c) * 64 + d] = lo + hi;
    }
    __syncthreads();

    // cross-chunk reduce + normalize + write (640 outputs)
    for (int e = t; e < NQB * D_; e += 512) {
        int i = e >> 6, dd = e & 63;
        float inv = 1.0f / s_red[NQB + i];
        float tot = 0.0f;
#pragma unroll
        for (int cc = 0; cc < 8; cc++) tot += s_vout[(i * 8 + cc) * 64 + dd];
        int qx = __ldg(&g_top[bh * NS + grp * NQB + i]);
        out[(((size_t)b * L_ + qx) * H_ + h) * D_ + dd] = tot * inv;
    }
}

extern "C" void kernel_launch(void* const* d_in, const int* in_sizes, int n_in,
                              void* d_out, int out_size) {
    const float* q = (const float*)d_in[0];
    const float* k = (const float*)d_in[1];
    const float* v = (const float*)d_in[2];
    float* out = (float*)d_out;

    static const size_t upd_smem =
        (size_t)(NQB * L_ + NQB * D_ + NQB * 8 * D_ + 2 * NQB) * sizeof(float);
    cudaFuncSetAttribute(kernel_update, cudaFuncAttributeMaxDynamicSharedMemorySize, (int)upd_smem);

    kernel_vmean_init<<<NBH * 4, 512>>>(v, out);
    kernel_M<<<B_ * L_, 256>>>(q, k);
    kernel_topk<<<NBH, 256>>>();
    kernel_update<<<NBH * NGRP, 512, upd_smem>>>(q, k, v, out);
}

// round 14
// speedup vs baseline: 2.3267x; 1.0116x over previous
#include <cuda_runtime.h>
#include <cstdint>

#define B_   4
#define L_   2048
#define H_   8
#define D_   64
#define NS   40
#define NBH  (B_*H_)
#define NQB  10          // queries per update block
#define NGRP 4           // groups -> grid 128 (single wave on 148 SMs)

__device__ float g_M[NBH*L_];
__device__ int   g_top[NBH*NS];

// ---------------- packed f32x2 helpers ----------------
__device__ __forceinline__ void fma2(unsigned long long& d,
                                     unsigned long long a, unsigned long long b) {
    asm("fma.rn.f32x2 %0, %1, %2, %0;" : "+l"(d) : "l"(a), "l"(b));
}
__device__ __forceinline__ unsigned long long pack2(float lo, float hi) {
    unsigned long long r;
    asm("mov.b64 %0, {%1, %2};" : "=l"(r) : "f"(lo), "f"(hi));
    return r;
}
__device__ __forceinline__ void unpack2(unsigned long long p, float& lo, float& hi) {
    asm("mov.b64 {%0, %1}, %2;" : "=f"(lo), "=f"(hi) : "l"(p));
}

// ---------------- threefry2x32 ----------------
__device__ __forceinline__ uint32_t rotl32(uint32_t x, int r) {
    return (x << r) | (x >> (32 - r));
}
__device__ __forceinline__ void threefry2x32(uint32_t k0, uint32_t k1,
                                             uint32_t c0, uint32_t c1,
                                             uint32_t& o0, uint32_t& o1) {
    uint32_t ks0 = k0, ks1 = k1, ks2 = k0 ^ k1 ^ 0x1BD11BDAu;
    uint32_t x0 = c0 + ks0, x1 = c1 + ks1;
#define TF_RND(R) { x0 += x1; x1 = rotl32(x1, R); x1 ^= x0; }
    TF_RND(13) TF_RND(15) TF_RND(26) TF_RND(6)  x0 += ks1; x1 += ks2 + 1u;
    TF_RND(17) TF_RND(29) TF_RND(16) TF_RND(24) x0 += ks2; x1 += ks0 + 2u;
    TF_RND(13) TF_RND(15) TF_RND(26) TF_RND(6)  x0 += ks0; x1 += ks1 + 3u;
    TF_RND(17) TF_RND(29) TF_RND(16) TF_RND(24) x0 += ks1; x1 += ks2 + 4u;
    TF_RND(13) TF_RND(15) TF_RND(26) TF_RND(6)  x0 += ks2; x1 += ks0 + 5u;
#undef TF_RND
    o0 = x0; o1 = x1;
}

// K1: M = max - mean of sampled dots. Block=(b,q), warp=head.
__global__ void kernel_M(const float* __restrict__ q, const float* __restrict__ k) {
    int blk = blockIdx.x;
    int b   = blk >> 11;
    int qi  = blk & (L_ - 1);
    int w   = threadIdx.x >> 5;
    int lane = threadIdx.x & 31;
    int g = lane >> 3;
    int r = lane & 7;

    __shared__ int sidx[NS];
    if (threadIdx.x < NS) {
        uint32_t k20, k21;
        threefry2x32(0u, 42u, 0u, 1u, k20, k21);
        uint32_t a, bb;
        threefry2x32(k20, k21, 0u, (uint32_t)(qi * NS + threadIdx.x), a, bb);
        sidx[threadIdx.x] = (int)((a ^ bb) & 2047u);
    }
    __syncthreads();

    const float4* q4 = (const float4*)(q + (((size_t)blk) * H_ + w) * D_);
    float4 qa = q4[r], qb = q4[r + 8];

    const float4* kbase = (const float4*)k + ((size_t)b * L_) * (H_ * D_ / 4) + w * (D_ / 4);

    float mx = -INFINITY, sm = 0.0f;
#pragma unroll 5
    for (int s0 = 0; s0 < NS; s0 += 4) {
        int j = sidx[s0 + g];
        const float4* kr = kbase + (size_t)j * (H_ * D_ / 4);
        float4 ka = __ldcg(&kr[r]);
        float4 kb = __ldcg(&kr[r + 8]);
        float p = ka.x * qa.x + ka.y * qa.y + ka.z * qa.z + ka.w * qa.w
                + kb.x * qb.x + kb.y * qb.y + kb.z * qb.z + kb.w * qb.w;
        p += __shfl_xor_sync(0xffffffffu, p, 4);
        p += __shfl_xor_sync(0xffffffffu, p, 2);
        p += __shfl_xor_sync(0xffffffffu, p, 1);
        mx = fmaxf(mx, p);
        sm += p;
    }
    mx = fmaxf(mx, __shfl_xor_sync(0xffffffffu, mx, 8));
    mx = fmaxf(mx, __shfl_xor_sync(0xffffffffu, mx, 16));
    sm += __shfl_xor_sync(0xffffffffu, sm, 8);
    sm += __shfl_xor_sync(0xffffffffu, sm, 16);
    if (lane == 0) g_M[(b * H_ + w) * L_ + qi] = mx - sm * (1.0f / (float)NS);
}

// K2: top-40 per (b,h). (unchanged)
__global__ void kernel_topk() {
    int bh = blockIdx.x, t = threadIdx.x;
    float vals[8];
#pragma unroll
    for (int i = 0; i < 8; i++) vals[i] = g_M[bh * L_ + t * 8 + i];

    __shared__ float wv[8];
    __shared__ int   wi[8];
    __shared__ int   sbi;
    int warp = t >> 5, lane = t & 31;

    for (int u = 0; u < NS; u++) {
        float bv = -INFINITY; int bi = 1 << 30;
#pragma unroll
        for (int i = 0; i < 8; i++) {
            if (vals[i] > bv) { bv = vals[i]; bi = t * 8 + i; }
        }
#pragma unroll
        for (int o = 16; o; o >>= 1) {
            float ov = __shfl_xor_sync(0xffffffffu, bv, o);
            int   oi = __shfl_xor_sync(0xffffffffu, bi, o);
            if (ov > bv || (ov == bv && oi < bi)) { bv = ov; bi = oi; }
        }
        if (lane == 0) { wv[warp] = bv; wi[warp] = bi; }
        __syncthreads();
        if (t == 0) {
            float fb = wv[0]; int fi = wi[0];
#pragma unroll
            for (int wd = 1; wd < 8; wd++) {
                if (wv[wd] > fb || (wv[wd] == fb && wi[wd] < fi)) { fb = wv[wd]; fi = wi[wd]; }
            }
            g_top[bh * NS + u] = fi;
            sbi = fi;
        }
        __syncthreads();
        int fi = sbi;
        if ((fi >> 3) == t) vals[fi & 7] = -INFINITY;
        __syncthreads();
    }
}

// K3: fused V_mean + broadcast-init. (unchanged)
__global__ __launch_bounds__(512) void kernel_vmean_init(const float* __restrict__ v,
                                                         float* __restrict__ out) {
    __shared__ float4 sred[512];
    __shared__ float4 vm4[16];
    int bh = blockIdx.x >> 2, quarter = blockIdx.x & 3;
    int b = bh >> 3, h = bh & 7;
    int t = threadIdx.x;
    int d4 = t & 15, r = t >> 4;

    const float4* v4 = (const float4*)v;
    size_t base = ((size_t)b * L_) * (H_ * D_ / 4) + h * (D_ / 4) + d4;
    float4 acc = make_float4(0.f, 0.f, 0.f, 0.f);
#pragma unroll 8
    for (int it = 0; it < L_ / 32; it++) {
        float4 x = __ldg(&v4[base + (size_t)(it * 32 + r) * (H_ * D_ / 4)]);
        acc.x += x.x; acc.y += x.y; acc.z += x.z; acc.w += x.w;
    }
    sred[t] = acc;
    __syncthreads();
    for (int o = 256; o >= 16; o >>= 1) {
        if (t < o) {
            float4 a = sred[t], bb = sred[t + o];
            a.x += bb.x; a.y += bb.y; a.z += bb.z; a.w += bb.w;
            sred[t] = a;
        }
        __syncthreads();
    }
    if (t < 16) {
        float4 s = sred[t];
        const float inv = 1.0f / (float)L_;
        s.x *= inv; s.y *= inv; s.z *= inv; s.w *= inv;
        vm4[t] = s;
    }
    __syncthreads();
    float4* out4 = (float4*)out;
    for (int e = t; e < 512 * 16; e += 512) {
        int l = quarter * 512 + (e >> 4), c = e & 15;
        out4[(((size_t)b * L_ + l) * H_ + h) * 16 + c] = vm4[c];
    }
}

// K4: dense attention, 10 queries/block, grid 128 (single wave). 512 threads.
// R13 structure + __ldcg streaming + scale folded into q staging.
__global__ __launch_bounds__(512) void kernel_update(const float* __restrict__ q,
                                                     const float* __restrict__ k,
                                                     const float* __restrict__ v,
                                                     float* __restrict__ out) {
    extern __shared__ float sh[];
    float* s_sc   = sh;                     // NQB * 2048
    float* s_q    = s_sc + NQB * L_;        // NQB * 64 (pre-scaled by 0.125)
    float* s_vout = s_q + NQB * D_;         // NQB * 8 * 64
    float* s_red  = s_vout + NQB * 8 * D_;  // 2*NQB (m, l)

    int bx  = blockIdx.x;
    int bh  = bx >> 2;
    int grp = bx & 3;
    int b = bh >> 3, h = bh & 7;
    int t = threadIdx.x;
    int w = t >> 5, lane = t & 31;

    // stage the 10 selected q rows, pre-scaled by 1/sqrt(D)=0.125
    for (int e = t; e < NQB * D_; e += 512) {
        int i = e >> 6, d = e & 63;
        int qx = __ldg(&g_top[bh * NS + grp * NQB + i]);
        s_q[e] = q[(((size_t)b * L_ + qx) * H_ + h) * D_ + d] * 0.125f;
    }
    __syncthreads();

    // scores: 10 q x 2048 k, packed f32x2, K streamed via .cg
    const ulonglong2* k16 = (const ulonglong2*)k;
    const ulonglong2* q16 = (const ulonglong2*)s_q;
#pragma unroll 1
    for (int rep = 0; rep < 4; rep++) {
        int j = rep * 512 + t;
        const ulonglong2* kr = k16 + (((size_t)b * L_ + j) * H_ + h) * 16;
        unsigned long long acc2[NQB];
#pragma unroll
        for (int i = 0; i < NQB; i++) acc2[i] = 0ull;
#pragma unroll
        for (int dv = 0; dv < 16; dv++) {
            ulonglong2 kv = __ldcg(&kr[dv]);
#pragma unroll
            for (int i = 0; i < NQB; i++) {
                ulonglong2 qv = q16[i * 16 + dv];
                fma2(acc2[i], kv.x, qv.x);
                fma2(acc2[i], kv.y, qv.y);
            }
        }
#pragma unroll
        for (int i = 0; i < NQB; i++) {
            float lo, hi; unpack2(acc2[i], lo, hi);
            s_sc[i * L_ + j] = lo + hi;
        }
    }
    __syncthreads();

    // softmax: warp w owns row w (w < NQB), full 2048 row
    if (w < NQB) {
        float* sc = s_sc + w * L_;
        float m = -INFINITY;
#pragma unroll
        for (int ii = 0; ii < 64; ii++) m = fmaxf(m, sc[ii * 32 + lane]);
#pragma unroll
        for (int o = 16; o; o >>= 1) m = fmaxf(m, __shfl_xor_sync(0xffffffffu, m, o));
        float l = 0.0f;
#pragma unroll
        for (int ii = 0; ii < 64; ii++) {
            int jj = ii * 32 + lane;
            float e = __expf(sc[jj] - m);
            sc[jj] = e;
            l += e;
        }
#pragma unroll
        for (int o = 16; o; o >>= 1) l += __shfl_xor_sync(0xffffffffu, l, o);
        if (lane == 0) { s_red[w] = m; s_red[NQB + w] = l; }
    }
    __syncthreads();

    // attn @ V (unnormalized): d = t&63, key-chunk c = t>>6 (8 chunks of 256).
    // 4 keys/iter; V streamed via .cg; scores via broadcast LDS.128.
    int d = t & 63, c = t >> 6;
    unsigned long long accu[NQB];
#pragma unroll
    for (int i = 0; i < NQB; i++) accu[i] = 0ull;
    const float* vb = v + (((size_t)b * L_ + c * 256) * H_ + h) * D_ + d;
#pragma unroll 2
    for (int jj = 0; jj < 64; jj++) {
        float v0 = __ldcg(&vb[(size_t)(jj * 4 + 0) * (H_ * D_)]);
        float v1 = __ldcg(&vb[(size_t)(jj * 4 + 1) * (H_ * D_)]);
        float v2 = __ldcg(&vb[(size_t)(jj * 4 + 2) * (H_ * D_)]);
        float v3 = __ldcg(&vb[(size_t)(jj * 4 + 3) * (H_ * D_)]);
        unsigned long long vp01 = pack2(v0, v1);
        unsigned long long vp23 = pack2(v2, v3);
        int j0 = c * 256 + jj * 4;
#pragma unroll
        for (int i = 0; i < NQB; i++) {
            ulonglong2 ap = *(const ulonglong2*)(s_sc + i * L_ + j0);
            fma2(accu[i], ap.x, vp01);
            fma2(accu[i], ap.y, vp23);
        }
    }
#pragma unroll
    for (int i = 0; i < NQB; i++) {
        float lo, hi; unpack2(accu[i], lo, hi);
        s_vout[(i * 8 + c) * 64 + d] = lo + hi;
    }
    __syncthreads();

    // cross-chunk reduce + normalize + write (640 outputs)
    for (int e = t; e < NQB * D_; e += 512) {
        int i = e >> 6, dd = e & 63;
        float inv = 1.0f / s_red[NQB + i];
        float tot = 0.0f;
#pragma unroll
        for (int cc = 0; cc < 8; cc++) tot += s_vout[(i * 8 + cc) * 64 + dd];
        int qx = __ldg(&g_top[bh * NS + grp * NQB + i]);
        out[(((size_t)b * L_ + qx) * H_ + h) * D_ + dd] = tot * inv;
    }
}

extern "C" void kernel_launch(void* const* d_in, const int* in_sizes, int n_in,
                              void* d_out, int out_size) {
    const float* q = (const float*)d_in[0];
    const float* k = (const float*)d_in[1];
    const float* v = (const float*)d_in[2];
    float* out = (float*)d_out;

    static const size_t upd_smem =
        (size_t)(NQB * L_ + NQB * D_ + NQB * 8 * D_ + 2 * NQB) * sizeof(float);
    cudaFuncSetAttribute(kernel_update, cudaFuncAttributeMaxDynamicSharedMemorySize, (int)upd_smem);

    kernel_vmean_init<<<NBH * 4, 512>>>(v, out);
    kernel_M<<<B_ * L_, 256>>>(q, k);
    kernel_topk<<<NBH, 256>>>();
    kernel_update<<<NBH * NGRP, 512, upd_smem>>>(q, k, v, out);
}

// round 15
// speedup vs baseline: 2.3928x; 1.0284x over previous
#include <cuda_runtime.h>
#include <cstdint>

#define B_   4
#define L_   2048
#define H_   8
#define D_   64
#define NS   40
#define NBH  (B_*H_)
#define NQB  10          // queries per update block
#define NGRP 4           // groups -> grid 128 (single wave on 148 SMs)

__device__ float g_M[NBH*L_];
__device__ int   g_top[NBH*NS];

// ---------------- packed f32x2 helpers ----------------
__device__ __forceinline__ void fma2(unsigned long long& d,
                                     unsigned long long a, unsigned long long b) {
    asm("fma.rn.f32x2 %0, %1, %2, %0;" : "+l"(d) : "l"(a), "l"(b));
}
__device__ __forceinline__ unsigned long long pack2(float lo, float hi) {
    unsigned long long r;
    asm("mov.b64 %0, {%1, %2};" : "=l"(r) : "f"(lo), "f"(hi));
    return r;
}
__device__ __forceinline__ void unpack2(unsigned long long p, float& lo, float& hi) {
    asm("mov.b64 {%0, %1}, %2;" : "=f"(lo), "=f"(hi) : "l"(p));
}

// ---------------- threefry2x32 ----------------
__device__ __forceinline__ uint32_t rotl32(uint32_t x, int r) {
    return (x << r) | (x >> (32 - r));
}
__device__ __forceinline__ void threefry2x32(uint32_t k0, uint32_t k1,
                                             uint32_t c0, uint32_t c1,
                                             uint32_t& o0, uint32_t& o1) {
    uint32_t ks0 = k0, ks1 = k1, ks2 = k0 ^ k1 ^ 0x1BD11BDAu;
    uint32_t x0 = c0 + ks0, x1 = c1 + ks1;
#define TF_RND(R) { x0 += x1; x1 = rotl32(x1, R); x1 ^= x0; }
    TF_RND(13) TF_RND(15) TF_RND(26) TF_RND(6)  x0 += ks1; x1 += ks2 + 1u;
    TF_RND(17) TF_RND(29) TF_RND(16) TF_RND(24) x0 += ks2; x1 += ks0 + 2u;
    TF_RND(13) TF_RND(15) TF_RND(26) TF_RND(6)  x0 += ks0; x1 += ks1 + 3u;
    TF_RND(17) TF_RND(29) TF_RND(16) TF_RND(24) x0 += ks1; x1 += ks2 + 4u;
    TF_RND(13) TF_RND(15) TF_RND(26) TF_RND(6)  x0 += ks2; x1 += ks0 + 5u;
#undef TF_RND
    o0 = x0; o1 = x1;
}

// K1: M = max - mean of sampled dots. Block=(b,q), warp=head. (R14, unchanged)
__global__ void kernel_M(const float* __restrict__ q, const float* __restrict__ k) {
    int blk = blockIdx.x;
    int b   = blk >> 11;
    int qi  = blk & (L_ - 1);
    int w   = threadIdx.x >> 5;
    int lane = threadIdx.x & 31;
    int g = lane >> 3;
    int r = lane & 7;

    __shared__ int sidx[NS];
    if (threadIdx.x < NS) {
        uint32_t k20, k21;
        threefry2x32(0u, 42u, 0u, 1u, k20, k21);
        uint32_t a, bb;
        threefry2x32(k20, k21, 0u, (uint32_t)(qi * NS + threadIdx.x), a, bb);
        sidx[threadIdx.x] = (int)((a ^ bb) & 2047u);
    }
    __syncthreads();

    const float4* q4 = (const float4*)(q + (((size_t)blk) * H_ + w) * D_);
    float4 qa = q4[r], qb = q4[r + 8];

    const float4* kbase = (const float4*)k + ((size_t)b * L_) * (H_ * D_ / 4) + w * (D_ / 4);

    float mx = -INFINITY, sm = 0.0f;
#pragma unroll 5
    for (int s0 = 0; s0 < NS; s0 += 4) {
        int j = sidx[s0 + g];
        const float4* kr = kbase + (size_t)j * (H_ * D_ / 4);
        float4 ka = __ldcg(&kr[r]);
        float4 kb = __ldcg(&kr[r + 8]);
        float p = ka.x * qa.x + ka.y * qa.y + ka.z * qa.z + ka.w * qa.w
                + kb.x * qb.x + kb.y * qb.y + kb.z * qb.z + kb.w * qb.w;
        p += __shfl_xor_sync(0xffffffffu, p, 4);
        p += __shfl_xor_sync(0xffffffffu, p, 2);
        p += __shfl_xor_sync(0xffffffffu, p, 1);
        mx = fmaxf(mx, p);
        sm += p;
    }
    mx = fmaxf(mx, __shfl_xor_sync(0xffffffffu, mx, 8));
    mx = fmaxf(mx, __shfl_xor_sync(0xffffffffu, mx, 16));
    sm += __shfl_xor_sync(0xffffffffu, sm, 8);
    sm += __shfl_xor_sync(0xffffffffu, sm, 16);
    if (lane == 0) g_M[(b * H_ + w) * L_ + qi] = mx - sm * (1.0f / (float)NS);
}

// K2: top-40 per (b,h). (unchanged)
__global__ void kernel_topk() {
    int bh = blockIdx.x, t = threadIdx.x;
    float vals[8];
#pragma unroll
    for (int i = 0; i < 8; i++) vals[i] = g_M[bh * L_ + t * 8 + i];

    __shared__ float wv[8];
    __shared__ int   wi[8];
    __shared__ int   sbi;
    int warp = t >> 5, lane = t & 31;

    for (int u = 0; u < NS; u++) {
        float bv = -INFINITY; int bi = 1 << 30;
#pragma unroll
        for (int i = 0; i < 8; i++) {
            if (vals[i] > bv) { bv = vals[i]; bi = t * 8 + i; }
        }
#pragma unroll
        for (int o = 16; o; o >>= 1) {
            float ov = __shfl_xor_sync(0xffffffffu, bv, o);
            int   oi = __shfl_xor_sync(0xffffffffu, bi, o);
            if (ov > bv || (ov == bv && oi < bi)) { bv = ov; bi = oi; }
        }
        if (lane == 0) { wv[warp] = bv; wi[warp] = bi; }
        __syncthreads();
        if (t == 0) {
            float fb = wv[0]; int fi = wi[0];
#pragma unroll
            for (int wd = 1; wd < 8; wd++) {
                if (wv[wd] > fb || (wv[wd] == fb && wi[wd] < fi)) { fb = wv[wd]; fi = wi[wd]; }
            }
            g_top[bh * NS + u] = fi;
            sbi = fi;
        }
        __syncthreads();
        int fi = sbi;
        if ((fi >> 3) == t) vals[fi & 7] = -INFINITY;
        __syncthreads();
    }
}

// K3: fused V_mean + broadcast-init. (unchanged)
__global__ __launch_bounds__(512) void kernel_vmean_init(const float* __restrict__ v,
                                                         float* __restrict__ out) {
    __shared__ float4 sred[512];
    __shared__ float4 vm4[16];
    int bh = blockIdx.x >> 2, quarter = blockIdx.x & 3;
    int b = bh >> 3, h = bh & 7;
    int t = threadIdx.x;
    int d4 = t & 15, r = t >> 4;

    const float4* v4 = (const float4*)v;
    size_t base = ((size_t)b * L_) * (H_ * D_ / 4) + h * (D_ / 4) + d4;
    float4 acc = make_float4(0.f, 0.f, 0.f, 0.f);
#pragma unroll 8
    for (int it = 0; it < L_ / 32; it++) {
        float4 x = __ldg(&v4[base + (size_t)(it * 32 + r) * (H_ * D_ / 4)]);
        acc.x += x.x; acc.y += x.y; acc.z += x.z; acc.w += x.w;
    }
    sred[t] = acc;
    __syncthreads();
    for (int o = 256; o >= 16; o >>= 1) {
        if (t < o) {
            float4 a = sred[t], bb = sred[t + o];
            a.x += bb.x; a.y += bb.y; a.z += bb.z; a.w += bb.w;
            sred[t] = a;
        }
        __syncthreads();
    }
    if (t < 16) {
        float4 s = sred[t];
        const float inv = 1.0f / (float)L_;
        s.x *= inv; s.y *= inv; s.z *= inv; s.w *= inv;
        vm4[t] = s;
    }
    __syncthreads();
    float4* out4 = (float4*)out;
    for (int e = t; e < 512 * 16; e += 512) {
        int l = quarter * 512 + (e >> 4), c = e & 15;
        out4[(((size_t)b * L_ + l) * H_ + h) * 16 + c] = vm4[c];
    }
}

// K4: dense attention, 10 queries/block, grid 128 (single wave). 512 threads. (R14)
__global__ __launch_bounds__(512) void kernel_update(const float* __restrict__ q,
                                                     const float* __restrict__ k,
                                                     const float* __restrict__ v,
                                                     float* __restrict__ out) {
    extern __shared__ float sh[];
    float* s_sc   = sh;                     // NQB * 2048
    float* s_q    = s_sc + NQB * L_;        // NQB * 64 (pre-scaled by 0.125)
    float* s_vout = s_q + NQB * D_;         // NQB * 8 * 64
    float* s_red  = s_vout + NQB * 8 * D_;  // NQB (l sums)

    int bx  = blockIdx.x;
    int bh  = bx >> 2;
    int grp = bx & 3;
    int b = bh >> 3, h = bh & 7;
    int t = threadIdx.x;
    int w = t >> 5, lane = t & 31;

    // stage the 10 selected q rows, pre-scaled by 1/sqrt(D)=0.125
    for (int e = t; e < NQB * D_; e += 512) {
        int i = e >> 6, d = e & 63;
        int qx = __ldg(&g_top[bh * NS + grp * NQB + i]);
        s_q[e] = q[(((size_t)b * L_ + qx) * H_ + h) * D_ + d] * 0.125f;
    }
    __syncthreads();

    // scores: 10 q x 2048 k, packed f32x2, K streamed via .cg
    const ulonglong2* k16 = (const ulonglong2*)k;
    const ulonglong2* q16 = (const ulonglong2*)s_q;
#pragma unroll 1
    for (int rep = 0; rep < 4; rep++) {
        int j = rep * 512 + t;
        const ulonglong2* kr = k16 + (((size_t)b * L_ + j) * H_ + h) * 16;
        unsigned long long acc2[NQB];
#pragma unroll
        for (int i = 0; i < NQB; i++) acc2[i] = 0ull;
#pragma unroll
        for (int dv = 0; dv < 16; dv++) {
            ulonglong2 kv = __ldcg(&kr[dv]);
#pragma unroll
            for (int i = 0; i < NQB; i++) {
                ulonglong2 qv = q16[i * 16 + dv];
                fma2(acc2[i], kv.x, qv.x);
                fma2(acc2[i], kv.y, qv.y);
            }
        }
#pragma unroll
        for (int i = 0; i < NQB; i++) {
            float lo, hi; unpack2(acc2[i], lo, hi);
            s_sc[i * L_ + j] = lo + hi;
        }
    }
    __syncthreads();

    // softmax: warp w owns row w (w < NQB), full 2048 row
    if (w < NQB) {
        float* sc = s_sc + w * L_;
        float m = -INFINITY;
#pragma unroll
        for (int ii = 0; ii < 64; ii++) m = fmaxf(m, sc[ii * 32 + lane]);
#pragma unroll
        for (int o = 16; o; o >>= 1) m = fmaxf(m, __shfl_xor_sync(0xffffffffu, m, o));
        float l = 0.0f;
#pragma unroll
        for (int ii = 0; ii < 64; ii++) {
            int jj = ii * 32 + lane;
            float e = __expf(sc[jj] - m);
            sc[jj] = e;
            l += e;
        }
#pragma unroll
        for (int o = 16; o; o >>= 1) l += __shfl_xor_sync(0xffffffffu, l, o);
        if (lane == 0) s_red[w] = l;
    }
    __syncthreads();

    // attn @ V (unnormalized): d = t&63, key-chunk c = t>>6 (8 chunks of 256).
    // 4 keys/iter; V streamed via .cg; scores via broadcast LDS.128.
    int d = t & 63, c = t >> 6;
    unsigned long long accu[NQB];
#pragma unroll
    for (int i = 0; i < NQB; i++) accu[i] = 0ull;
    const float* vb = v + (((size_t)b * L_ + c * 256) * H_ + h) * D_ + d;
#pragma unroll 2
    for (int jj = 0; jj < 64; jj++) {
        float v0 = __ldcg(&vb[(size_t)(jj * 4 + 0) * (H_ * D_)]);
        float v1 = __ldcg(&vb[(size_t)(jj * 4 + 1) * (H_ * D_)]);
        float v2 = __ldcg(&vb[(size_t)(jj * 4 + 2) * (H_ * D_)]);
        float v3 = __ldcg(&vb[(size_t)(jj * 4 + 3) * (H_ * D_)]);
        unsigned long long vp01 = pack2(v0, v1);
        unsigned long long vp23 = pack2(v2, v3);
        int j0 = c * 256 + jj * 4;
#pragma unroll
        for (int i = 0; i < NQB; i++) {
            ulonglong2 ap = *(const ulonglong2*)(s_sc + i * L_ + j0);
            fma2(accu[i], ap.x, vp01);
            fma2(accu[i], ap.y, vp23);
        }
    }
#pragma unroll
    for (int i = 0; i < NQB; i++) {
        float lo, hi; unpack2(accu[i], lo, hi);
        s_vout[(i * 8 + c) * 64 + d] = lo + hi;
    }
    __syncthreads();

    // cross-chunk reduce + normalize + write (640 outputs)
    for (int e = t; e < NQB * D_; e += 512) {
        int i = e >> 6, dd = e & 63;
        float inv = 1.0f / s_red[i];
        float tot = 0.0f;
#pragma unroll
        for (int cc = 0; cc < 8; cc++) tot += s_vout[(i * 8 + cc) * 64 + dd];
        int qx = __ldg(&g_top[bh * NS + grp * NQB + i]);
        out[(((size_t)b * L_ + qx) * H_ + h) * D_ + dd] = tot * inv;
    }
}

extern "C" void kernel_launch(void* const* d_in, const int* in_sizes, int n_in,
                              void* d_out, int out_size) {
    const float* q = (const float*)d_in[0];
    const float* k = (const float*)d_in[1];
    const float* v = (const float*)d_in[2];
    float* out = (float*)d_out;

    // One-time setup (first call is the uncaptured correctness run).
    static cudaStream_t s2 = nullptr;
    static cudaEvent_t evFork = nullptr, evJoin = nullptr;
    static bool attrs_set = false;
    static const size_t upd_smem =
        (size_t)(NQB * L_ + NQB * D_ + NQB * 8 * D_ + NQB) * sizeof(float);
    if (!attrs_set) {
        cudaFuncSetAttribute(kernel_update, cudaFuncAttributeMaxDynamicSharedMemorySize,
                             (int)upd_smem);
        cudaStreamCreateWithFlags(&s2, cudaStreamNonBlocking);
        cudaEventCreateWithFlags(&evFork, cudaEventDisableTiming);
        cudaEventCreateWithFlags(&evJoin, cudaEventDisableTiming);
        attrs_set = true;
    }

    // Fork: vmean_init on side stream, M->topk on main stream, join before update.
    cudaEventRecord(evFork, 0);
    cudaStreamWaitEvent(s2, evFork, 0);
    kernel_vmean_init<<<NBH * 4, 512, 0, s2>>>(v, out);
    cudaEventRecord(evJoin, s2);

    kernel_M<<<B_ * L_, 256>>>(q, k);
    kernel_topk<<<NBH, 256>>>();

    cudaStreamWaitEvent(0, evJoin, 0);
    kernel_update<<<NBH * NGRP, 512, upd_smem>>>(q, k, v, out);
}

// round 16
// speedup vs baseline: 2.4719x; 1.0330x over previous
#include <cuda_runtime.h>
#include <cstdint>

#define B_   4
#define L_   2048
#define H_   8
#define D_   64
#define NS   40
#define NBH  (B_*H_)
#define NQB  10          // queries per update block
#define NGRP 4           // groups -> grid 128 (single wave on 148 SMs)
#define SUBT 256         // K subtile tokens (QK staging)
#define KSTR 68          // staged K row stride in floats (272B: conflict-free)

__device__ float g_M[NBH*L_];
__device__ int   g_top[NBH*NS];

// ---------------- packed f32x2 helpers ----------------
__device__ __forceinline__ void fma2(unsigned long long& d,
                                     unsigned long long a, unsigned long long b) {
    asm("fma.rn.f32x2 %0, %1, %2, %0;" : "+l"(d) : "l"(a), "l"(b));
}
__device__ __forceinline__ unsigned long long pack2(float lo, float hi) {
    unsigned long long r;
    asm("mov.b64 %0, {%1, %2};" : "=l"(r) : "f"(lo), "f"(hi));
    return r;
}
__device__ __forceinline__ void unpack2(unsigned long long p, float& lo, float& hi) {
    asm("mov.b64 {%0, %1}, %2;" : "=f"(lo), "=f"(hi) : "l"(p));
}

// ---------------- threefry2x32 ----------------
__device__ __forceinline__ uint32_t rotl32(uint32_t x, int r) {
    return (x << r) | (x >> (32 - r));
}
__device__ __forceinline__ void threefry2x32(uint32_t k0, uint32_t k1,
                                             uint32_t c0, uint32_t c1,
                                             uint32_t& o0, uint32_t& o1) {
    uint32_t ks0 = k0, ks1 = k1, ks2 = k0 ^ k1 ^ 0x1BD11BDAu;
    uint32_t x0 = c0 + ks0, x1 = c1 + ks1;
#define TF_RND(R) { x0 += x1; x1 = rotl32(x1, R); x1 ^= x0; }
    TF_RND(13) TF_RND(15) TF_RND(26) TF_RND(6)  x0 += ks1; x1 += ks2 + 1u;
    TF_RND(17) TF_RND(29) TF_RND(16) TF_RND(24) x0 += ks2; x1 += ks0 + 2u;
    TF_RND(13) TF_RND(15) TF_RND(26) TF_RND(6)  x0 += ks0; x1 += ks1 + 3u;
    TF_RND(17) TF_RND(29) TF_RND(16) TF_RND(24) x0 += ks1; x1 += ks2 + 4u;
    TF_RND(13) TF_RND(15) TF_RND(26) TF_RND(6)  x0 += ks2; x1 += ks0 + 5u;
#undef TF_RND
    o0 = x0; o1 = x1;
}

// K1: M = max - mean of sampled dots. Block=(b,q), warp=head. (unchanged)
__global__ void kernel_M(const float* __restrict__ q, const float* __restrict__ k) {
    int blk = blockIdx.x;
    int b   = blk >> 11;
    int qi  = blk & (L_ - 1);
    int w   = threadIdx.x >> 5;
    int lane = threadIdx.x & 31;
    int g = lane >> 3;
    int r = lane & 7;

    __shared__ int sidx[NS];
    if (threadIdx.x < NS) {
        uint32_t k20, k21;
        threefry2x32(0u, 42u, 0u, 1u, k20, k21);
        uint32_t a, bb;
        threefry2x32(k20, k21, 0u, (uint32_t)(qi * NS + threadIdx.x), a, bb);
        sidx[threadIdx.x] = (int)((a ^ bb) & 2047u);
    }
    __syncthreads();

    const float4* q4 = (const float4*)(q + (((size_t)blk) * H_ + w) * D_);
    float4 qa = q4[r], qb = q4[r + 8];

    const float4* kbase = (const float4*)k + ((size_t)b * L_) * (H_ * D_ / 4) + w * (D_ / 4);

    float mx = -INFINITY, sm = 0.0f;
#pragma unroll 5
    for (int s0 = 0; s0 < NS; s0 += 4) {
        int j = sidx[s0 + g];
        const float4* kr = kbase + (size_t)j * (H_ * D_ / 4);
        float4 ka = __ldcg(&kr[r]);
        float4 kb = __ldcg(&kr[r + 8]);
        float p = ka.x * qa.x + ka.y * qa.y + ka.z * qa.z + ka.w * qa.w
                + kb.x * qb.x + kb.y * qb.y + kb.z * qb.z + kb.w * qb.w;
        p += __shfl_xor_sync(0xffffffffu, p, 4);
        p += __shfl_xor_sync(0xffffffffu, p, 2);
        p += __shfl_xor_sync(0xffffffffu, p, 1);
        mx = fmaxf(mx, p);
        sm += p;
    }
    mx = fmaxf(mx, __shfl_xor_sync(0xffffffffu, mx, 8));
    mx = fmaxf(mx, __shfl_xor_sync(0xffffffffu, mx, 16));
    sm += __shfl_xor_sync(0xffffffffu, sm, 8);
    sm += __shfl_xor_sync(0xffffffffu, sm, 16);
    if (lane == 0) g_M[(b * H_ + w) * L_ + qi] = mx - sm * (1.0f / (float)NS);
}

// K2: top-40 per (b,h). (unchanged)
__global__ void kernel_topk() {
    int bh = blockIdx.x, t = threadIdx.x;
    float vals[8];
#pragma unroll
    for (int i = 0; i < 8; i++) vals[i] = g_M[bh * L_ + t * 8 + i];

    __shared__ float wv[8];
    __shared__ int   wi[8];
    __shared__ int   sbi;
    int warp = t >> 5, lane = t & 31;

    for (int u = 0; u < NS; u++) {
        float bv = -INFINITY; int bi = 1 << 30;
#pragma unroll
        for (int i = 0; i < 8; i++) {
            if (vals[i] > bv) { bv = vals[i]; bi = t * 8 + i; }
        }
#pragma unroll
        for (int o = 16; o; o >>= 1) {
            float ov = __shfl_xor_sync(0xffffffffu, bv, o);
            int   oi = __shfl_xor_sync(0xffffffffu, bi, o);
            if (ov > bv || (ov == bv && oi < bi)) { bv = ov; bi = oi; }
        }
        if (lane == 0) { wv[warp] = bv; wi[warp] = bi; }
        __syncthreads();
        if (t == 0) {
            float fb = wv[0]; int fi = wi[0];
#pragma unroll
            for (int wd = 1; wd < 8; wd++) {
                if (wv[wd] > fb || (wv[wd] == fb && wi[wd] < fi)) { fb = wv[wd]; fi = wi[wd]; }
            }
            g_top[bh * NS + u] = fi;
            sbi = fi;
        }
        __syncthreads();
        int fi = sbi;
        if ((fi >> 3) == t) vals[fi & 7] = -INFINITY;
        __syncthreads();
    }
}

// K3: fused V_mean + broadcast-init. (unchanged)
__global__ __launch_bounds__(512) void kernel_vmean_init(const float* __restrict__ v,
                                                         float* __restrict__ out) {
    __shared__ float4 sred[512];
    __shared__ float4 vm4[16];
    int bh = blockIdx.x >> 2, quarter = blockIdx.x & 3;
    int b = bh >> 3, h = bh & 7;
    int t = threadIdx.x;
    int d4 = t & 15, r = t >> 4;

    const float4* v4 = (const float4*)v;
    size_t base = ((size_t)b * L_) * (H_ * D_ / 4) + h * (D_ / 4) + d4;
    float4 acc = make_float4(0.f, 0.f, 0.f, 0.f);
#pragma unroll 8
    for (int it = 0; it < L_ / 32; it++) {
        float4 x = __ldg(&v4[base + (size_t)(it * 32 + r) * (H_ * D_ / 4)]);
        acc.x += x.x; acc.y += x.y; acc.z += x.z; acc.w += x.w;
    }
    sred[t] = acc;
    __syncthreads();
    for (int o = 256; o >= 16; o >>= 1) {
        if (t < o) {
            float4 a = sred[t], bb = sred[t + o];
            a.x += bb.x; a.y += bb.y; a.z += bb.z; a.w += bb.w;
            sred[t] = a;
        }
        __syncthreads();
    }
    if (t < 16) {
        float4 s = sred[t];
        const float inv = 1.0f / (float)L_;
        s.x *= inv; s.y *= inv; s.z *= inv; s.w *= inv;
        vm4[t] = s;
    }
    __syncthreads();
    float4* out4 = (float4*)out;
    for (int e = t; e < 512 * 16; e += 512) {
        int l = quarter * 512 + (e >> 4), c = e & 15;
        out4[(((size_t)b * L_ + l) * H_ + h) * 16 + c] = vm4[c];
    }
}

// K4: dense attention, 10 queries/block, grid 128 (single wave). 512 threads.
// QK phase: K staged through smem (coalesced LDG, conflict-free LDS).
__global__ __launch_bounds__(512) void kernel_update(const float* __restrict__ q,
                                                     const float* __restrict__ k,
                                                     const float* __restrict__ v,
                                                     float* __restrict__ out) {
    extern __shared__ float sh[];
    float* s_sc   = sh;                     // NQB * 2048
    float* s_q    = s_sc + NQB * L_;        // NQB * 64 (pre-scaled by 0.125)
    float* s_vout = s_q + NQB * D_;         // NQB * 8 * 64
    float* s_red  = s_vout + NQB * 8 * D_;  // NQB (l sums) + pad
    float* s_K    = s_red + 16;             // SUBT * KSTR (68KB staging)

    int bx  = blockIdx.x;
    int bh  = bx >> 2;
    int grp = bx & 3;
    int b = bh >> 3, h = bh & 7;
    int t = threadIdx.x;
    int w = t >> 5, lane = t & 31;

    // stage the 10 selected q rows, pre-scaled by 1/sqrt(D)=0.125
    for (int e = t; e < NQB * D_; e += 512) {
        int i = e >> 6, d = e & 63;
        int qx = __ldg(&g_top[bh * NS + grp * NQB + i]);
        s_q[e] = q[(((size_t)b * L_ + qx) * H_ + h) * D_ + d] * 0.125f;
    }

    // scores: 8 subtiles of 256 tokens; thread = (token t&255, query-half t>>8)
    const float4* k4g = (const float4*)k;
    const ulonglong2* q16 = (const ulonglong2*)s_q;
    int tok   = t & 255;
    int qbase = (t >> 8) * 5;
#pragma unroll 1
    for (int sub = 0; sub < L_ / SUBT; sub++) {
        __syncthreads();
        // stage K subtile: 256 tokens x 16 float4, coalesced, 272B row stride
        for (int e = t; e < SUBT * 16; e += 512) {
            int rr = e >> 4, cc = e & 15;
            ((float4*)s_K)[rr * 17 + cc] =
                __ldcg(&k4g[(((size_t)b * L_ + sub * SUBT + rr) * H_ + h) * 16 + cc]);
        }
        __syncthreads();
        unsigned long long acc2[5];
#pragma unroll
        for (int i = 0; i < 5; i++) acc2[i] = 0ull;
        const ulonglong2* kr = (const ulonglong2*)(s_K + tok * KSTR);
#pragma unroll
        for (int dv = 0; dv < 16; dv++) {
            ulonglong2 kv = kr[dv];
#pragma unroll
            for (int i = 0; i < 5; i++) {
                ulonglong2 qv = q16[(qbase + i) * 16 + dv];
                fma2(acc2[i], kv.x, qv.x);
                fma2(acc2[i], kv.y, qv.y);
            }
        }
        int j = sub * SUBT + tok;
#pragma unroll
        for (int i = 0; i < 5; i++) {
            float lo, hi; unpack2(acc2[i], lo, hi);
            s_sc[(qbase + i) * L_ + j] = lo + hi;
        }
    }
    __syncthreads();

    // softmax: warp w owns row w (w < NQB), full 2048 row
    if (w < NQB) {
        float* sc = s_sc + w * L_;
        float m = -INFINITY;
#pragma unroll
        for (int ii = 0; ii < 64; ii++) m = fmaxf(m, sc[ii * 32 + lane]);
#pragma unroll
        for (int o = 16; o; o >>= 1) m = fmaxf(m, __shfl_xor_sync(0xffffffffu, m, o));
        float l = 0.0f;
#pragma unroll
        for (int ii = 0; ii < 64; ii++) {
            int jj = ii * 32 + lane;
            float e = __expf(sc[jj] - m);
            sc[jj] = e;
            l += e;
        }
#pragma unroll
        for (int o = 16; o; o >>= 1) l += __shfl_xor_sync(0xffffffffu, l, o);
        if (lane == 0) s_red[w] = l;
    }
    __syncthreads();

    // attn @ V (unnormalized): d = t&63, key-chunk c = t>>6 (8 chunks of 256).
    // 4 keys/iter; V streamed via .cg; scores via broadcast LDS.128.
    int d = t & 63, c = t >> 6;
    unsigned long long accu[NQB];
#pragma unroll
    for (int i = 0; i < NQB; i++) accu[i] = 0ull;
    const float* vb = v + (((size_t)b * L_ + c * 256) * H_ + h) * D_ + d;
#pragma unroll 2
    for (int jj = 0; jj < 64; jj++) {
        float v0 = __ldcg(&vb[(size_t)(jj * 4 + 0) * (H_ * D_)]);
        float v1 = __ldcg(&vb[(size_t)(jj * 4 + 1) * (H_ * D_)]);
        float v2 = __ldcg(&vb[(size_t)(jj * 4 + 2) * (H_ * D_)]);
        float v3 = __ldcg(&vb[(size_t)(jj * 4 + 3) * (H_ * D_)]);
        unsigned long long vp01 = pack2(v0, v1);
        unsigned long long vp23 = pack2(v2, v3);
        int j0 = c * 256 + jj * 4;
#pragma unroll
        for (int i = 0; i < NQB; i++) {
            ulonglong2 ap = *(const ulonglong2*)(s_sc + i * L_ + j0);
            fma2(accu[i], ap.x, vp01);
            fma2(accu[i], ap.y, vp23);
        }
    }
#pragma unroll
    for (int i = 0; i < NQB; i++) {
        float lo, hi; unpack2(accu[i], lo, hi);
        s_vout[(i * 8 + c) * 64 + d] = lo + hi;
    }
    __syncthreads();

    // cross-chunk reduce + normalize + write (640 outputs)
    for (int e = t; e < NQB * D_; e += 512) {
        int i = e >> 6, dd = e & 63;
        float inv = 1.0f / s_red[i];
        float tot = 0.0f;
#pragma unroll
        for (int cc = 0; cc < 8; cc++) tot += s_vout[(i * 8 + cc) * 64 + dd];
        int qx = __ldg(&g_top[bh * NS + grp * NQB + i]);
        out[(((size_t)b * L_ + qx) * H_ + h) * D_ + dd] = tot * inv;
    }
}

extern "C" void kernel_launch(void* const* d_in, const int* in_sizes, int n_in,
                              void* d_out, int out_size) {
    const float* q = (const float*)d_in[0];
    const float* k = (const float*)d_in[1];
    const float* v = (const float*)d_in[2];
    float* out = (float*)d_out;

    static cudaStream_t s2 = nullptr;
    static cudaEvent_t evFork = nullptr, evJoin = nullptr;
    static bool attrs_set = false;
    static const size_t upd_smem =
        (size_t)(NQB * L_ + NQB * D_ + NQB * 8 * D_ + 16 + SUBT * KSTR) * sizeof(float);
    if (!attrs_set) {
        cudaFuncSetAttribute(kernel_update, cudaFuncAttributeMaxDynamicSharedMemorySize,
                             (int)upd_smem);
        cudaStreamCreateWithFlags(&s2, cudaStreamNonBlocking);
        cudaEventCreateWithFlags(&evFork, cudaEventDisableTiming);
        cudaEventCreateWithFlags(&evJoin, cudaEventDisableTiming);
        attrs_set = true;
    }

    // Fork: vmean_init on side stream, M->topk on main stream, join before update.
    cudaEventRecord(evFork, 0);
    cudaStreamWaitEvent(s2, evFork, 0);
    kernel_vmean_init<<<NBH * 4, 512, 0, s2>>>(v, out);
    cudaEventRecord(evJoin, s2);

    kernel_M<<<B_ * L_, 256>>>(q, k);
    kernel_topk<<<NBH, 256>>>();

    cudaStreamWaitEvent(0, evJoin, 0);
    kernel_update<<<NBH * NGRP, 512, upd_smem>>>(q, k, v, out);
}